// round 12
// baseline (speedup 1.0000x reference)
#include <cuda_runtime.h>
#include <stdint.h>

#define BATCH   8192
#define IN_DIM  1024
#define N_HID   2048
#define OUT_DIM 256
#define S2      3072
#define NT1     16        // 1024/64 source tiles
#define NT2     48        // 3072/64
#define ECAP    16        // Bin(64,.05): mean 3.2, 7.3 sigma
#define BTS     64        // batch sub-tile (32 lanes x float2)
#define BTE     128       // effective batch tile (2 sub-buffers)

// ---- scratch (static device globals: allocation-free) ----
__device__ float    g_xT[(size_t)IN_DIM * BATCH];                 // w * x, transposed
__device__ float    g_hT[(size_t)N_HID * BATCH];                  // w * hidden, transposed
__device__ uint16_t g_et1[(size_t)NT1 * N_HID * ECAP];            // [tile][row][ECAP]
__device__ uint16_t g_et2[(size_t)NT2 * OUT_DIM * ECAP];
__device__ uint16_t g_ct1[(size_t)NT1 * N_HID];                   // [tile][row]
__device__ uint16_t g_ct2[(size_t)NT2 * OUT_DIM];

// ---- helpers ----
__device__ __forceinline__ void cpa16(uint32_t dst, const void* src) {
    asm volatile("cp.async.cg.shared.global [%0], [%1], 16;" :: "r"(dst), "l"(src));
}
#define CP_COMMIT() asm volatile("cp.async.commit_group;")
#define CP_WAIT0()  asm volatile("cp.async.wait_group 0;")

__device__ __forceinline__ float ftanh(float x) {
    float r; asm("tanh.approx.f32 %0, %1;" : "=f"(r) : "f"(x)); return r;
}
__device__ __forceinline__ void addp(unsigned long long& a, unsigned long long b) {
    asm("add.rn.f32x2 %0, %0, %1;" : "+l"(a) : "l"(b));
}

// ------------------------------------------------------------------
// Build tile-major edge lists (64-wide tiles). Entry = s_in_tile*4 +
// (code-1) <= 255; layer kernels shift <<8 (256B per (src,act) row).
// ------------------------------------------------------------------
__global__ void build_edges_kernel(const int* __restrict__ mat) {
    int row  = blockIdx.x;
    int lane = threadIdx.x & 31, warp = threadIdx.x >> 5;  // 256 thr
    bool is2 = (row >= N_HID);
    int ntiles = is2 ? NT2 : NT1;
    int rows   = is2 ? OUT_DIM : N_HID;
    int rloc   = is2 ? row - N_HID : row;
    const int* mrow = mat + (size_t)row * S2;
    uint16_t* et = is2 ? g_et2 : g_et1;
    uint16_t* ct = is2 ? g_ct2 : g_ct1;
    unsigned lt = (1u << lane) - 1u;

    for (int t = warp; t < ntiles; t += 8) {
        int cnt = 0;
        uint16_t* dst = et + ((size_t)t * rows + rloc) * ECAP;
        for (int c = 0; c < 2; ++c) {     // 64-wide tile = 2 ballots
            int code = mrow[t * 64 + c * 32 + lane];
            unsigned m = __ballot_sync(0xffffffffu, code != 0);
            int p = cnt + __popc(m & lt);
            if (code && p < ECAP)
                dst[p] = (uint16_t)(((c * 32 + lane) << 2) | (code - 1));
            cnt += __popc(m);
        }
        if (lane == 0) ct[(size_t)t * rows + rloc] = (uint16_t)(cnt < ECAP ? cnt : ECAP);
    }
}

// ------------------------------------------------------------------
// Transpose x [B][IN] -> g_xT [IN][B], pre-scaled by w.
// ------------------------------------------------------------------
__global__ void transpose_kernel(const float* __restrict__ x, const float* __restrict__ wp) {
    __shared__ float tile[32][33];
    float w = *wp;
    int i0 = blockIdx.x * 32, b0 = blockIdx.y * 32;
    int tx = threadIdx.x, ty = threadIdx.y;   // 32 x 8
#pragma unroll
    for (int k = 0; k < 32; k += 8)
        tile[ty + k][tx] = w * x[(size_t)(b0 + ty + k) * IN_DIM + i0 + tx];
    __syncthreads();
#pragma unroll
    for (int k = 0; k < 32; k += 8)
        g_xT[(size_t)(i0 + ty + k) * BATCH + b0 + tx] = tile[tx][ty + k];
}

// ------------------------------------------------------------------
// Layer kernel: 1024 threads, fp32 planes as TWO batch sub-buffers of
// [64 srcs][4 acts][64 cols] (64KB each, compile-time 64KB apart).
// Each edge: one address calc, two LDS.64 (2nd at +65536 immediate),
// two f32x2 adds -> 2.25 instr/value. Edges+counts cp.async double-
// buffered; counts preloaded to registers; fill via reg-prefetch+MUFU.
// ------------------------------------------------------------------
template<int NT, int NPW, int ROWS, bool IS_L1>
__global__ void __launch_bounds__(1024, 1)
layer_kernel(const float* __restrict__ wp, float* __restrict__ dout) {
    constexpr int NODES = 32 * NPW;
    extern __shared__ char smraw[];
    uint32_t sbase = (uint32_t)__cvta_generic_to_shared(smraw);
    float*    planes = (float*)smraw;                            // 2 x 64KB
    uint16_t* ed[2]; ed[0] = (uint16_t*)(smraw + 131072); ed[1] = ed[0] + NODES * ECAP;
    uint16_t* cn[2]; cn[0] = ed[1] + NODES * ECAP;        cn[1] = cn[0] + NODES;
    uint32_t ed_a[2] = { sbase + 131072, sbase + 131072 + NODES * ECAP * 2 };
    uint32_t cn_a[2] = { sbase + 131072 + 2 * NODES * ECAP * 2,
                         sbase + 131072 + 2 * NODES * ECAP * 2 + NODES * 2 };

    int r0   = blockIdx.x * NODES;
    int b0   = blockIdx.y * BTE;
    int tid  = threadIdx.x;
    int warp = tid >> 5, lane = tid & 31;

    const uint16_t* get = IS_L1 ? g_et1 : g_et2;
    const uint16_t* gct = IS_L1 ? g_ct1 : g_ct2;

#define STAGE(TT, B)                                                                   \
    {                                                                                  \
        if (tid < NODES * 2)                                                           \
            cpa16(ed_a[B] + tid * 16, get + ((size_t)(TT) * ROWS + r0) * ECAP + tid * 8); \
        if (tid < NODES / 8)                                                           \
            cpa16(cn_a[B] + tid * 16, gct + (size_t)(TT) * ROWS + r0 + tid * 8);       \
    }

    STAGE(0, 0);
    CP_COMMIT();

    unsigned long long acc[NPW][2];
#pragma unroll
    for (int n = 0; n < NPW; ++n) { acc[n][0] = 0ULL; acc[n][1] = 0ULL; }

    // fill tasks: 2 sub-bufs x 64 srcs x 16 float4-chunks = 2048, 2/thread
    // k selects the sub-buffer; ls = src (0..63), c4 = col chunk (0..60)
    float4 pf[2];
#define LOADF(T)                                                                   \
    {                                                                              \
        _Pragma("unroll")                                                          \
        for (int k = 0; k < 2; ++k) {                                              \
            int ls = tid >> 4, c4 = (tid & 15) << 2;                               \
            int s0 = (T) * 64;                                                     \
            const float* gb = (IS_L1 || s0 < IN_DIM)                               \
                ? g_xT + (size_t)s0 * BATCH                                        \
                : g_hT + (size_t)(s0 - IN_DIM) * BATCH;                            \
            pf[k] = __ldg((const float4*)(gb + (size_t)ls * BATCH + b0 + k * BTS + c4)); \
        }                                                                          \
    }

    LOADF(0);
    CP_WAIT0();
    __syncthreads();

    const char* pbase = (const char*)planes + lane * 8;

    for (int t = 0; t < NT; ++t) {
        int cur = t & 1;
        // ---- fill both sub-buffers for tile t from prefetched regs ----
#pragma unroll
        for (int k = 0; k < 2; ++k) {
            int ls = tid >> 4, c4 = (tid & 15) << 2;
            float4 xv = pf[k];
            float4 p1, p2, p3;
            p1.x = fmaxf(xv.x, 0.0f); p1.y = fmaxf(xv.y, 0.0f);
            p1.z = fmaxf(xv.z, 0.0f); p1.w = fmaxf(xv.w, 0.0f);
            p2.x = ftanh(xv.x); p2.y = ftanh(xv.y); p2.z = ftanh(xv.z); p2.w = ftanh(xv.w);
            p3.x = fmaf(0.5f, ftanh(0.5f * xv.x), 0.5f);
            p3.y = fmaf(0.5f, ftanh(0.5f * xv.y), 0.5f);
            p3.z = fmaf(0.5f, ftanh(0.5f * xv.z), 0.5f);
            p3.w = fmaf(0.5f, ftanh(0.5f * xv.w), 0.5f);
            float* pr = planes + k * 16384 + ls * 256 + c4;  // 256 floats/src
            *(float4*)(pr)       = xv;
            *(float4*)(pr + 64)  = p1;
            *(float4*)(pr + 128) = p2;
            *(float4*)(pr + 192) = p3;
        }
        if (t + 1 < NT) { STAGE(t + 1, cur ^ 1); }
        CP_COMMIT();
        __syncthreads();   // planes(t) ready

        if (t + 1 < NT) LOADF(t + 1);

        // ---- edge phase: one addr calc serves both sub-buffers ----
        const uint32_t* ebuf = (const uint32_t*)ed[cur];
        uint32_t cw[(NPW + 1) / 2];
        if constexpr (NPW == 8) {
            uint4 c4p = *(const uint4*)(cn[cur] + warp * 8);
            cw[0] = c4p.x; cw[1] = c4p.y; cw[2] = c4p.z; cw[3] = c4p.w;
        } else {
            uint2 c2p = *(const uint2*)(cn[cur] + warp * 4);
            cw[0] = c2p.x; cw[1] = c2p.y;
        }
#pragma unroll
        for (int n = 0; n < NPW; ++n) {
            int cnt = (cw[n >> 1] >> ((n & 1) * 16)) & 0xffff;
            const uint32_t* ep = ebuf + (warp * NPW + n) * (ECAP / 2);
            int np = cnt >> 1;
            for (int j = 0; j < np; ++j) {
                uint32_t u = ep[j];
                const char* pa = pbase + ((u & 0xffffu) << 8);
                const char* pb = pbase + ((u >> 16) << 8);
                addp(acc[n][0], *(const unsigned long long*)(pa));
                addp(acc[n][1], *(const unsigned long long*)(pa + 65536));
                addp(acc[n][0], *(const unsigned long long*)(pb));
                addp(acc[n][1], *(const unsigned long long*)(pb + 65536));
            }
            if (cnt & 1) {
                uint32_t u = ep[np] & 0xffffu;
                const char* pa = pbase + (u << 8);
                addp(acc[n][0], *(const unsigned long long*)(pa));
                addp(acc[n][1], *(const unsigned long long*)(pa + 65536));
            }
        }
        CP_WAIT0();        // edges(t+1) landed
        __syncthreads();   // edge(t) done -> planes reusable
    }

    // ---- epilogue ----
    if (IS_L1) {
        float w = *wp;   // g_hT holds w * hidden for layer2's fill
#pragma unroll
        for (int n = 0; n < NPW; ++n) {
            int r = r0 + warp * NPW + n;
#pragma unroll
            for (int sb = 0; sb < 2; ++sb) {
                float2 v = *(float2*)&acc[n][sb];
                float2 q; q.x = w * v.x; q.y = w * v.y;
                *(float2*)&g_hT[(size_t)r * BATCH + b0 + sb * BTS + lane * 2] = q;
            }
        }
    } else {
#pragma unroll
        for (int n = 0; n < NPW; ++n) {
            int r = r0 + warp * NPW + n;
#pragma unroll
            for (int sb = 0; sb < 2; ++sb) {
                float2 v = *(float2*)&acc[n][sb];
                dout[(size_t)(b0 + sb * BTS + lane * 2 + 0) * OUT_DIM + r] = v.x;
                dout[(size_t)(b0 + sb * BTS + lane * 2 + 1) * OUT_DIM + r] = v.y;
            }
        }
    }
#undef STAGE
#undef LOADF
}

// smem: planes 128KB + 2 edge buffers + 2 count buffers
#define SMEM_L1 (131072 + 2 * 256 * ECAP * 2 + 2 * 256 * 2)   // 148480
#define SMEM_L2 (131072 + 2 * 128 * ECAP * 2 + 2 * 128 * 2)   // 139776

extern "C" void kernel_launch(void* const* d_in, const int* in_sizes, int n_in,
                              void* d_out, int out_size) {
    const float* x   = (const float*)d_in[0];
    const float* wp  = (const float*)d_in[1];
    const int*   mat = (const int*)d_in[2];
    float*       out = (float*)d_out;

    // L1: NODES=256 (NPW=8), grid (8 row-tiles, 64 batch-groups)
    auto k1 = layer_kernel<NT1, 8, N_HID, true>;
    // L2: NODES=128 (NPW=4), grid (2 row-tiles, 64 batch-groups)
    auto k2 = layer_kernel<NT2, 4, OUT_DIM, false>;

    cudaFuncSetAttribute(k1, cudaFuncAttributeMaxDynamicSharedMemorySize, SMEM_L1);
    cudaFuncSetAttribute(k2, cudaFuncAttributeMaxDynamicSharedMemorySize, SMEM_L2);

    build_edges_kernel<<<N_HID + OUT_DIM, 256>>>(mat);
    transpose_kernel<<<dim3(IN_DIM / 32, BATCH / 32), dim3(32, 8)>>>(x, wp);

    // adjacent bids (x-fastest) share the batch-group -> g_xT slab L2-hot
    k1<<<dim3(N_HID / 256, BATCH / BTE), 1024, SMEM_L1>>>(wp, nullptr);
    k2<<<dim3(OUT_DIM / 128, BATCH / BTE), 1024, SMEM_L2>>>(wp, out);
}

// round 13
// speedup vs baseline: 1.0169x; 1.0169x over previous
#include <cuda_runtime.h>
#include <stdint.h>

#define BATCH   8192
#define IN_DIM  1024
#define N_HID   2048
#define OUT_DIM 256
#define S2      3072
#define NT1     8         // 1024/128 source tiles
#define NT2     24        // 3072/128
#define ECAP    24        // Bin(128,.05): mean 6.4, sd 2.47 -> 7.1 sigma
#define BT      64        // batch tile: 32 lanes x float2
#define ZENT    512       // dummy entry -> zeroed 256B slot at planes+128KB

// ---- scratch (static device globals: allocation-free) ----
__device__ float    g_xT[(size_t)IN_DIM * BATCH];                 // w * x, transposed
__device__ float    g_hT[(size_t)N_HID * BATCH];                  // w * hidden, transposed
__device__ uint16_t g_et1[(size_t)NT1 * N_HID * ECAP];            // [tile][row][ECAP]
__device__ uint16_t g_et2[(size_t)NT2 * OUT_DIM * ECAP];
__device__ uint16_t g_ct1[(size_t)NT1 * N_HID];                   // [tile][row] PAIR counts
__device__ uint16_t g_ct2[(size_t)NT2 * OUT_DIM];

// ---- helpers ----
__device__ __forceinline__ void cpa16(uint32_t dst, const void* src) {
    asm volatile("cp.async.cg.shared.global [%0], [%1], 16;" :: "r"(dst), "l"(src));
}
#define CP_COMMIT() asm volatile("cp.async.commit_group;")
#define CP_WAIT0()  asm volatile("cp.async.wait_group 0;")

__device__ __forceinline__ float ftanh(float x) {
    float r; asm("tanh.approx.f32 %0, %1;" : "=f"(r) : "f"(x)); return r;
}
__device__ __forceinline__ void addp(unsigned long long& a, unsigned long long b) {
    asm("add.rn.f32x2 %0, %0, %1;" : "+l"(a) : "l"(b));
}

// ------------------------------------------------------------------
// Build tile-major edge lists (128-wide tiles). Entry = s_in_tile*4 +
// (code-1) <= 511; kernels shift <<8. Odd rows padded with ZENT and
// counts stored as PAIRS -> branch-free inner loop. Deterministic.
// ------------------------------------------------------------------
__global__ void build_edges_kernel(const int* __restrict__ mat) {
    int row  = blockIdx.x;
    int lane = threadIdx.x & 31, warp = threadIdx.x >> 5;  // 256 thr
    bool is2 = (row >= N_HID);
    int ntiles = is2 ? NT2 : NT1;
    int rows   = is2 ? OUT_DIM : N_HID;
    int rloc   = is2 ? row - N_HID : row;
    const int* mrow = mat + (size_t)row * S2;
    uint16_t* et = is2 ? g_et2 : g_et1;
    uint16_t* ct = is2 ? g_ct2 : g_ct1;
    unsigned lt = (1u << lane) - 1u;

    for (int t = warp; t < ntiles; t += 8) {
        int cnt = 0;
        uint16_t* dst = et + ((size_t)t * rows + rloc) * ECAP;
        for (int c = 0; c < 4; ++c) {      // 128-wide tile = 4 ballots
            int code = mrow[t * 128 + c * 32 + lane];
            unsigned m = __ballot_sync(0xffffffffu, code != 0);
            int p = cnt + __popc(m & lt);
            if (code && p < ECAP)
                dst[p] = (uint16_t)(((c * 32 + lane) << 2) | (code - 1));
            cnt += __popc(m);
        }
        if (lane == 0) {
            int c = cnt < ECAP ? cnt : ECAP;
            if (c & 1) dst[c] = ZENT;              // pad to even with zero-slot
            ct[(size_t)t * rows + rloc] = (uint16_t)((c + 1) >> 1);   // pairs
        }
    }
}

// ------------------------------------------------------------------
// Transpose x [B][IN] -> g_xT [IN][B], pre-scaled by w.
// ------------------------------------------------------------------
__global__ void transpose_kernel(const float* __restrict__ x, const float* __restrict__ wp) {
    __shared__ float tile[32][33];
    float w = *wp;
    int i0 = blockIdx.x * 32, b0 = blockIdx.y * 32;
    int tx = threadIdx.x, ty = threadIdx.y;   // 32 x 8
#pragma unroll
    for (int k = 0; k < 32; k += 8)
        tile[ty + k][tx] = w * x[(size_t)(b0 + ty + k) * IN_DIM + i0 + tx];
    __syncthreads();
#pragma unroll
    for (int k = 0; k < 32; k += 8)
        g_xT[(size_t)(i0 + ty + k) * BATCH + b0 + tx] = tile[tx][ty + k];
}

// ------------------------------------------------------------------
// Layer kernel: 1024 threads, fp32 planes [128 srcs][4 acts][64 cols]
// = 128KB + 256B zero slot. Edges+pair-counts double-buffered via
// cp.async; counts preloaded to registers; branch-free pair loop:
// per pair = 1 entry-u32 + 2 LDS.64 + 2 f32x2 adds. Fill via
// register-prefetch + MUFU (R6 proven shape).
// ------------------------------------------------------------------
template<int NT, int NPW, int ROWS, bool IS_L1>
__global__ void __launch_bounds__(1024, 1)
layer_kernel(const float* __restrict__ wp, float* __restrict__ dout) {
    constexpr int NODES = 32 * NPW;
    constexpr int EDB = NODES * ECAP * 2;          // edge buffer bytes
    extern __shared__ char smraw[];
    uint32_t sbase = (uint32_t)__cvta_generic_to_shared(smraw);
    float*    planes = (float*)smraw;                               // 128KB
    uint16_t* ed[2]; ed[0] = (uint16_t*)(smraw + 131328); ed[1] = (uint16_t*)(smraw + 131328 + EDB);
    uint16_t* cn[2]; cn[0] = (uint16_t*)(smraw + 131328 + 2 * EDB);
                     cn[1] = cn[0] + NODES;
    uint32_t ed_a[2] = { sbase + 131328, sbase + 131328 + EDB };
    uint32_t cn_a[2] = { sbase + 131328 + 2 * EDB, sbase + 131328 + 2 * EDB + NODES * 2 };

    int r0   = blockIdx.x * NODES;                 // row-tiles fastest
    int b0   = blockIdx.y * BT;
    int tid  = threadIdx.x;
    int warp = tid >> 5, lane = tid & 31;

    const uint16_t* get = IS_L1 ? g_et1 : g_et2;
    const uint16_t* gct = IS_L1 ? g_ct1 : g_ct2;

#define STAGE(TT, B)                                                                   \
    {                                                                                  \
        for (int i = tid; i < NODES * 3; i += 1024)                                    \
            cpa16(ed_a[B] + i * 16, get + ((size_t)(TT) * ROWS + r0) * ECAP + i * 8);  \
        if (tid < NODES / 8)                                                           \
            cpa16(cn_a[B] + tid * 16, gct + (size_t)(TT) * ROWS + r0 + tid * 8);       \
    }

    // zero the dummy slot (entry ZENT<<8 = 131072..131327)
    if (tid < 32) ((long long*)(smraw + 131072))[tid] = 0;

    STAGE(0, 0);
    CP_COMMIT();

    unsigned long long acc[NPW];
#pragma unroll
    for (int n = 0; n < NPW; ++n) acc[n] = 0ULL;

    // fill tasks: 128 srcs x 16 float4-chunks = 2048, 2 per thread
    float4 pf[2];
#define LOADF(T)                                                                 \
    {                                                                            \
        _Pragma("unroll")                                                        \
        for (int k = 0; k < 2; ++k) {                                            \
            int idx = tid + (k << 10);                                           \
            int ls = idx >> 4, c4 = (idx & 15) << 2;                             \
            int s0 = (T) * 128;                                                  \
            const float* gb = (IS_L1 || s0 < IN_DIM)                             \
                ? g_xT + (size_t)s0 * BATCH                                      \
                : g_hT + (size_t)(s0 - IN_DIM) * BATCH;                          \
            pf[k] = __ldg((const float4*)(gb + (size_t)ls * BATCH + b0 + c4));   \
        }                                                                        \
    }

    LOADF(0);
    CP_WAIT0();
    __syncthreads();

    const char* pbase = (const char*)planes + lane * 8;

    for (int t = 0; t < NT; ++t) {
        int cur = t & 1;
        // ---- fill planes(t) from prefetched regs ----
#pragma unroll
        for (int k = 0; k < 2; ++k) {
            int idx = tid + (k << 10);
            int ls = idx >> 4, c4 = (idx & 15) << 2;
            float4 xv = pf[k];
            float4 p1, p2, p3;
            p1.x = fmaxf(xv.x, 0.0f); p1.y = fmaxf(xv.y, 0.0f);
            p1.z = fmaxf(xv.z, 0.0f); p1.w = fmaxf(xv.w, 0.0f);
            p2.x = ftanh(xv.x); p2.y = ftanh(xv.y); p2.z = ftanh(xv.z); p2.w = ftanh(xv.w);
            p3.x = fmaf(0.5f, ftanh(0.5f * xv.x), 0.5f);
            p3.y = fmaf(0.5f, ftanh(0.5f * xv.y), 0.5f);
            p3.z = fmaf(0.5f, ftanh(0.5f * xv.z), 0.5f);
            p3.w = fmaf(0.5f, ftanh(0.5f * xv.w), 0.5f);
            float* pr = planes + ls * 256 + c4;   // 256 floats per src
            *(float4*)(pr)       = xv;
            *(float4*)(pr + 64)  = p1;
            *(float4*)(pr + 128) = p2;
            *(float4*)(pr + 192) = p3;
        }
        if (t + 1 < NT) { STAGE(t + 1, cur ^ 1); }
        CP_COMMIT();
        __syncthreads();   // planes(t) ready

        if (t + 1 < NT) LOADF(t + 1);

        // ---- edge phase: branch-free pair loop ----
        const uint32_t* ebuf = (const uint32_t*)ed[cur];
        uint32_t cw[NPW / 2];
        if constexpr (NPW == 16) {
            uint4 cA = *(const uint4*)(cn[cur] + warp * 16);
            uint4 cB = *(const uint4*)(cn[cur] + warp * 16 + 8);
            cw[0] = cA.x; cw[1] = cA.y; cw[2] = cA.z; cw[3] = cA.w;
            cw[4] = cB.x; cw[5] = cB.y; cw[6] = cB.z; cw[7] = cB.w;
        } else {
            uint4 cA = *(const uint4*)(cn[cur] + warp * 8);
            cw[0] = cA.x; cw[1] = cA.y; cw[2] = cA.z; cw[3] = cA.w;
        }
#pragma unroll
        for (int n = 0; n < NPW; ++n) {
            int np = (cw[n >> 1] >> ((n & 1) * 16)) & 0xffff;   // pairs
            const uint32_t* ep = ebuf + (warp * NPW + n) * (ECAP / 2);
            for (int j = 0; j < np; ++j) {
                uint32_t u = ep[j];
                addp(acc[n], *(const unsigned long long*)(pbase + ((u & 0xffffu) << 8)));
                addp(acc[n], *(const unsigned long long*)(pbase + ((u >> 16) << 8)));
            }
        }
        CP_WAIT0();        // edges(t+1) landed
        __syncthreads();   // edge(t) done -> planes reusable
    }

    // ---- epilogue ----
    if (IS_L1) {
        float w = *wp;   // g_hT holds w * hidden for layer2's fill
#pragma unroll
        for (int n = 0; n < NPW; ++n) {
            int r = r0 + warp * NPW + n;
            float2 v = *(float2*)&acc[n];
            float2 q; q.x = w * v.x; q.y = w * v.y;
            *(float2*)&g_hT[(size_t)r * BATCH + b0 + lane * 2] = q;
        }
    } else {
#pragma unroll
        for (int n = 0; n < NPW; ++n) {
            int r = r0 + warp * NPW + n;
            float2 v = *(float2*)&acc[n];
            dout[(size_t)(b0 + lane * 2 + 0) * OUT_DIM + r] = v.x;
            dout[(size_t)(b0 + lane * 2 + 1) * OUT_DIM + r] = v.y;
        }
    }
#undef STAGE
#undef LOADF
}

// smem: planes 128KB + zero slot 256B + 2 edge bufs + 2 count bufs
#define SMEM_L1 (131328 + 2 * 512 * ECAP * 2 + 2 * 512 * 2)   // 182528
#define SMEM_L2 (131328 + 2 * 256 * ECAP * 2 + 2 * 256 * 2)   // 156928

extern "C" void kernel_launch(void* const* d_in, const int* in_sizes, int n_in,
                              void* d_out, int out_size) {
    const float* x   = (const float*)d_in[0];
    const float* wp  = (const float*)d_in[1];
    const int*   mat = (const int*)d_in[2];
    float*       out = (float*)d_out;

    // L1: NODES=512 (NPW=16), grid (4 row-tiles, 128 batch) -> dup 4,
    //     row-tiles fastest so duplicating CTAs share g_xT slab in L2
    auto k1 = layer_kernel<NT1, 16, N_HID, true>;
    // L2: NODES=256 (NPW=8), grid (1, 128) -> dup 1
    auto k2 = layer_kernel<NT2, 8, OUT_DIM, false>;

    cudaFuncSetAttribute(k1, cudaFuncAttributeMaxDynamicSharedMemorySize, SMEM_L1);
    cudaFuncSetAttribute(k2, cudaFuncAttributeMaxDynamicSharedMemorySize, SMEM_L2);

    build_edges_kernel<<<N_HID + OUT_DIM, 256>>>(mat);
    transpose_kernel<<<dim3(IN_DIM / 32, BATCH / 32), dim3(32, 8)>>>(x, wp);

    k1<<<dim3(N_HID / 512, BATCH / BT), 1024, SMEM_L1>>>(wp, nullptr);
    k2<<<dim3(OUT_DIM / 256, BATCH / BT), 1024, SMEM_L2>>>(wp, out);
}